// round 1
// baseline (speedup 1.0000x reference)
#include <cuda_runtime.h>
#include <math.h>

#define Bq   8
#define Nn   3136
#define C1d  64
#define C2d  128
#define KVd  192
#define Hh   4
#define MLPd 256
#define NROW (Bq*Nn)     /* 25088 */
#define NCH  49          /* 3136 / 64 */
#define GSZ  (C1d*KVd)   /* 12288 */

// ---------------- scratch (device globals; no allocation) ----------------
__device__ float g_ea[NROW*KVd];          // 19.3 MB  LN(concat) rows
__device__ float g_cx1[NROW*C1d];         //  6.4 MB  LN(emb1) rows
__device__ float g_Gpart[Bq*NCH*GSZ];     // 19.3 MB  per-chunk partials of G
__device__ float g_G[Bq*GSZ];             //  G[b] = cx1^T @ ea
__device__ float g_T[Bq*Hh*GSZ];          //  T = Wq @ G
__device__ float g_S[Bq*Hh*GSZ];          //  scores -> probs (in place)
__device__ float g_Pp[Bq*Hh*GSZ];         //  probs @ Wv (per head)
__device__ float g_M[Bq*GSZ];             //  M[b] = Wout @ Pbar
__device__ float g_cx[NROW*C1d];          //  cx = emb1 + o

extern __shared__ float dsm[];

// ---------------- 1) dual LayerNorm ----------------
__global__ void ln_kernel(const float* __restrict__ emb1, const float* __restrict__ emb2,
                          const float* __restrict__ g1, const float* __restrict__ b1,
                          const float* __restrict__ gA, const float* __restrict__ bA) {
    int row = blockIdx.x;
    int t = threadIdx.x;                  // 0..191
    float v = (t < C1d) ? emb1[row*C1d + t] : emb2[row*C2d + (t - C1d)];
    float s = v, q = v*v;
    #pragma unroll
    for (int o = 16; o > 0; o >>= 1) {
        s += __shfl_down_sync(0xffffffffu, s, o);
        q += __shfl_down_sync(0xffffffffu, q, o);
    }
    __shared__ float ws[6], wq[6];
    int w = t >> 5;
    if ((t & 31) == 0) { ws[w] = s; wq[w] = q; }
    __syncthreads();
    float s1 = ws[0] + ws[1], q1 = wq[0] + wq[1];
    float sA = s1 + ws[2] + ws[3] + ws[4] + ws[5];
    float qA = q1 + wq[2] + wq[3] + wq[4] + wq[5];
    float mA = sA * (1.f/KVd);
    float vA = qA * (1.f/KVd) - mA*mA;
    float rA = rsqrtf(vA + 1e-6f);
    g_ea[row*KVd + t] = (v - mA) * rA * gA[t] + bA[t];
    if (t < C1d) {
        float m1 = s1 * (1.f/C1d);
        float v1 = q1 * (1.f/C1d) - m1*m1;
        float r1 = rsqrtf(v1 + 1e-6f);
        g_cx1[row*C1d + t] = (v - m1) * r1 * g1[t] + b1[t];
    }
}

// ---------------- 2) G partials: Gpart[b][ch] = sum over 64 rows of cx1^T ea ----
__global__ __launch_bounds__(256,1) void gmat_kernel() {
    float* sa = dsm;                 // [64][64]
    float* se = dsm + 64*64;         // [64][192]
    int ch = blockIdx.x, b = blockIdx.y;
    int tid = threadIdx.y*16 + threadIdx.x;
    int base = b*Nn + ch*64;
    for (int i = tid; i < 64*C1d; i += 256) sa[i] = g_cx1[base*C1d + i];
    for (int i = tid; i < 64*KVd; i += 256) se[i] = g_ea[base*KVd + i];
    __syncthreads();
    int cs = threadIdx.y*4, ks = threadIdx.x*12;
    float acc[4][12];
    #pragma unroll
    for (int j = 0; j < 4; j++)
        #pragma unroll
        for (int l = 0; l < 12; l++) acc[j][l] = 0.f;
    for (int r = 0; r < 64; r++) {
        float af[4], bf[12];
        #pragma unroll
        for (int j = 0; j < 4; j++) af[j] = sa[r*C1d + cs + j];
        #pragma unroll
        for (int l = 0; l < 12; l++) bf[l] = se[r*KVd + ks + l];
        #pragma unroll
        for (int j = 0; j < 4; j++)
            #pragma unroll
            for (int l = 0; l < 12; l++) acc[j][l] += af[j]*bf[l];
    }
    float* out = g_Gpart + (size_t)(b*NCH + ch)*GSZ;
    #pragma unroll
    for (int j = 0; j < 4; j++)
        #pragma unroll
        for (int l = 0; l < 12; l++) out[(cs+j)*KVd + ks + l] = acc[j][l];
}

// ---------------- 3) reduce chunks ----------------
__global__ void gred_kernel() {
    int idx = blockIdx.x*256 + threadIdx.x;   // < 8*12288
    int b = idx / GSZ, e = idx % GSZ;
    const float* p = g_Gpart + (size_t)b*NCH*GSZ + e;
    float s = 0.f;
    for (int ch = 0; ch < NCH; ch++) s += p[ch*GSZ];
    g_G[idx] = s;
}

// ---------------- 4) T = Wq[h] @ G[b] ----------------
__global__ __launch_bounds__(256,1) void tmat_kernel(const float* __restrict__ Wq) {
    float* sG = dsm;                 // [64][192]
    float* sW = dsm + 64*KVd;        // [64][64]
    int b = blockIdx.x >> 2, h = blockIdx.x & 3;
    int tid = threadIdx.y*16 + threadIdx.x;
    for (int i = tid; i < GSZ; i += 256) sG[i] = g_G[b*GSZ + i];
    for (int i = tid; i < C1d*C1d; i += 256) sW[i] = Wq[h*C1d*C1d + i];
    __syncthreads();
    int ds = threadIdx.y*4, ks = threadIdx.x*12;
    float acc[4][12];
    #pragma unroll
    for (int j = 0; j < 4; j++)
        #pragma unroll
        for (int l = 0; l < 12; l++) acc[j][l] = 0.f;
    for (int c = 0; c < 64; c++) {
        float wf[4], gf[12];
        #pragma unroll
        for (int j = 0; j < 4; j++) wf[j] = sW[(ds+j)*C1d + c];
        #pragma unroll
        for (int l = 0; l < 12; l++) gf[l] = sG[c*KVd + ks + l];
        #pragma unroll
        for (int j = 0; j < 4; j++)
            #pragma unroll
            for (int l = 0; l < 12; l++) acc[j][l] += wf[j]*gf[l];
    }
    float* out = g_T + (size_t)blockIdx.x*GSZ;
    #pragma unroll
    for (int j = 0; j < 4; j++)
        #pragma unroll
        for (int l = 0; l < 12; l++) out[(ds+j)*KVd + ks + l] = acc[j][l];
}

// ---------------- 5) S = T @ Wk^T / sqrt(KV) ----------------
__global__ __launch_bounds__(256,1) void smat_kernel(const float* __restrict__ Wk) {
    float* sT  = dsm;                // [64][200] padded
    float* sWk = dsm + 64*200;       // [48][201] padded
    int bh = blockIdx.x, h = bh & 3;
    int tile = blockIdx.y;           // 0..3, 48 k2 cols each
    int tid = threadIdx.y*16 + threadIdx.x;
    for (int i = tid; i < GSZ; i += 256) {
        int c = i / KVd, k = i % KVd;
        sT[c*200 + k] = g_T[(size_t)bh*GSZ + i];
    }
    for (int i = tid; i < 48*KVd; i += 256) {
        int r = i / KVd, k = i % KVd;
        sWk[r*201 + k] = Wk[(size_t)h*KVd*KVd + (tile*48 + r)*KVd + k];
    }
    __syncthreads();
    int cs = threadIdx.y*4, kl = threadIdx.x*3;
    float acc[4][3];
    #pragma unroll
    for (int j = 0; j < 4; j++)
        #pragma unroll
        for (int l = 0; l < 3; l++) acc[j][l] = 0.f;
    for (int kp = 0; kp < KVd; kp++) {
        float tf[4], wf[3];
        #pragma unroll
        for (int j = 0; j < 4; j++) tf[j] = sT[(cs+j)*200 + kp];
        #pragma unroll
        for (int l = 0; l < 3; l++) wf[l] = sWk[(kl+l)*201 + kp];
        #pragma unroll
        for (int j = 0; j < 4; j++)
            #pragma unroll
            for (int l = 0; l < 3; l++) acc[j][l] += tf[j]*wf[l];
    }
    const float scale = 0.0721687836487f;   // 1/sqrt(192)
    float* out = g_S + (size_t)bh*GSZ;
    #pragma unroll
    for (int j = 0; j < 4; j++)
        #pragma unroll
        for (int l = 0; l < 3; l++)
            out[(cs+j)*KVd + tile*48 + kl + l] = acc[j][l]*scale;
}

// ---------------- 6) InstanceNorm (two-pass) + softmax over 192, in place ----
__global__ void insoft_kernel() {
    int bh = blockIdx.x, t = threadIdx.x;
    float* S = g_S + (size_t)bh*GSZ;
    __shared__ float red[8];
    __shared__ float s_m, s_rs;
    int w = t >> 5, lane = t & 31;
    // pass 1: mean
    float s = 0.f;
    for (int i = t; i < GSZ; i += 256) s += S[i];
    #pragma unroll
    for (int o = 16; o > 0; o >>= 1) s += __shfl_down_sync(0xffffffffu, s, o);
    if (lane == 0) red[w] = s;
    __syncthreads();
    if (t == 0) {
        float tot = 0.f;
        for (int i = 0; i < 8; i++) tot += red[i];
        s_m = tot * (1.f/GSZ);
    }
    __syncthreads();
    float mean = s_m;
    // pass 2: variance
    float q = 0.f;
    for (int i = t; i < GSZ; i += 256) { float d = S[i] - mean; q += d*d; }
    #pragma unroll
    for (int o = 16; o > 0; o >>= 1) q += __shfl_down_sync(0xffffffffu, q, o);
    if (lane == 0) red[w] = q;
    __syncthreads();
    if (t == 0) {
        float tot = 0.f;
        for (int i = 0; i < 8; i++) tot += red[i];
        s_rs = rsqrtf(tot * (1.f/GSZ) + 1e-5f);
    }
    __syncthreads();
    float rs = s_rs;
    // softmax: warp w handles rows w, w+8, ...
    for (int r = w; r < C1d; r += 8) {
        float vals[6];
        float mx = -1e30f;
        #pragma unroll
        for (int mm = 0; mm < 6; mm++) {
            int k = lane + 32*mm;
            vals[mm] = (S[r*KVd + k] - mean) * rs;
            mx = fmaxf(mx, vals[mm]);
        }
        #pragma unroll
        for (int o = 16; o > 0; o >>= 1) mx = fmaxf(mx, __shfl_xor_sync(0xffffffffu, mx, o));
        float es = 0.f;
        #pragma unroll
        for (int mm = 0; mm < 6; mm++) { vals[mm] = expf(vals[mm] - mx); es += vals[mm]; }
        #pragma unroll
        for (int o = 16; o > 0; o >>= 1) es += __shfl_xor_sync(0xffffffffu, es, o);
        float inv = 1.f / es;
        #pragma unroll
        for (int mm = 0; mm < 6; mm++) S[r*KVd + lane + 32*mm] = vals[mm] * inv;
    }
}

// ---------------- 7) Pp[b,h] = probs @ Wv[h] ----------------
__global__ __launch_bounds__(256,1) void pmat_kernel(const float* __restrict__ Wv) {
    float* sP = dsm;                 // [64][200]
    float* sV = dsm + 64*200;        // [192][48]
    int bh = blockIdx.x, h = bh & 3, tile = blockIdx.y;
    int tid = threadIdx.y*16 + threadIdx.x;
    for (int i = tid; i < GSZ; i += 256) {
        int c = i / KVd, k = i % KVd;
        sP[c*200 + k] = g_S[(size_t)bh*GSZ + i];
    }
    for (int i = tid; i < KVd*48; i += 256) {
        int k2 = i / 48, col = i % 48;
        sV[k2*48 + col] = Wv[(size_t)h*KVd*KVd + k2*KVd + tile*48 + col];
    }
    __syncthreads();
    int cs = threadIdx.y*4, kl = threadIdx.x*3;
    float acc[4][3];
    #pragma unroll
    for (int j = 0; j < 4; j++)
        #pragma unroll
        for (int l = 0; l < 3; l++) acc[j][l] = 0.f;
    for (int k2 = 0; k2 < KVd; k2++) {
        float pf[4], vf[3];
        #pragma unroll
        for (int j = 0; j < 4; j++) pf[j] = sP[(cs+j)*200 + k2];
        #pragma unroll
        for (int l = 0; l < 3; l++) vf[l] = sV[k2*48 + kl + l];
        #pragma unroll
        for (int j = 0; j < 4; j++)
            #pragma unroll
            for (int l = 0; l < 3; l++) acc[j][l] += pf[j]*vf[l];
    }
    float* out = g_Pp + (size_t)bh*GSZ;
    #pragma unroll
    for (int j = 0; j < 4; j++)
        #pragma unroll
        for (int l = 0; l < 3; l++)
            out[(cs+j)*KVd + tile*48 + kl + l] = acc[j][l];
}

// ---------------- 8) M[b] = Wout @ Pbar[b] ----------------
__global__ __launch_bounds__(256,1) void mmat_kernel(const float* __restrict__ Wout) {
    float* sP = dsm;                 // [64][200]
    float* sW = dsm + 64*200;        // [64][64]
    int b = blockIdx.x;
    int tid = threadIdx.y*16 + threadIdx.x;
    for (int i = tid; i < GSZ; i += 256) {
        int c = i / KVd, k = i % KVd;
        float sum = g_Pp[(size_t)(b*Hh+0)*GSZ + i] + g_Pp[(size_t)(b*Hh+1)*GSZ + i]
                  + g_Pp[(size_t)(b*Hh+2)*GSZ + i] + g_Pp[(size_t)(b*Hh+3)*GSZ + i];
        sP[c*200 + k] = sum * 0.25f;
    }
    for (int i = tid; i < C1d*C1d; i += 256) sW[i] = Wout[i];
    __syncthreads();
    int ds = threadIdx.y*4, ks = threadIdx.x*12;
    float acc[4][12];
    #pragma unroll
    for (int j = 0; j < 4; j++)
        #pragma unroll
        for (int l = 0; l < 12; l++) acc[j][l] = 0.f;
    for (int c = 0; c < 64; c++) {
        float wf[4], pf[12];
        #pragma unroll
        for (int j = 0; j < 4; j++) wf[j] = sW[(ds+j)*C1d + c];
        #pragma unroll
        for (int l = 0; l < 12; l++) pf[l] = sP[c*200 + ks + l];
        #pragma unroll
        for (int j = 0; j < 4; j++)
            #pragma unroll
            for (int l = 0; l < 12; l++) acc[j][l] += wf[j]*pf[l];
    }
    float* out = g_M + (size_t)b*GSZ;
    #pragma unroll
    for (int j = 0; j < 4; j++)
        #pragma unroll
        for (int l = 0; l < 12; l++) out[(ds+j)*KVd + ks + l] = acc[j][l];
}

// ---------------- 9) cx = emb1 + ea @ M^T ----------------
__global__ __launch_bounds__(256,1) void octx_kernel(const float* __restrict__ emb1) {
    float* sE  = dsm;                // [64][200]
    float* sMt = dsm + 64*200;       // [192][65]  (M transposed)
    int ch = blockIdx.x, b = blockIdx.y;
    int base = b*Nn + ch*64;
    int tid = threadIdx.y*16 + threadIdx.x;
    for (int i = tid; i < GSZ; i += 256) {
        int r = i / KVd, k = i % KVd;
        sE[r*200 + k] = g_ea[(size_t)base*KVd + i];
    }
    for (int i = tid; i < GSZ; i += 256) {
        int c = i / KVd, k = i % KVd;
        sMt[k*65 + c] = g_M[(size_t)b*GSZ + i];
    }
    __syncthreads();
    int rs = threadIdx.y*4, cs = threadIdx.x*4;
    float acc[4][4];
    #pragma unroll
    for (int i = 0; i < 4; i++)
        #pragma unroll
        for (int j = 0; j < 4; j++) acc[i][j] = 0.f;
    for (int k = 0; k < KVd; k++) {
        float ef[4], mf[4];
        #pragma unroll
        for (int i = 0; i < 4; i++) ef[i] = sE[(rs+i)*200 + k];
        #pragma unroll
        for (int j = 0; j < 4; j++) mf[j] = sMt[k*65 + cs + j];
        #pragma unroll
        for (int i = 0; i < 4; i++)
            #pragma unroll
            for (int j = 0; j < 4; j++) acc[i][j] += ef[i]*mf[j];
    }
    #pragma unroll
    for (int i = 0; i < 4; i++) {
        int row = base + rs + i;
        #pragma unroll
        for (int j = 0; j < 4; j++)
            g_cx[(size_t)row*C1d + cs + j] = emb1[(size_t)row*C1d + cs + j] + acc[i][j];
    }
}

// ---------------- 10) fused FFN: out = fc2(gelu(fc1(LN(cx)))) + cx ----------
__device__ __forceinline__ float gelu_exact(float x) {
    return 0.5f * x * (1.f + erff(x * 0.70710678118654752f));
}

__global__ __launch_bounds__(256,1) void ffn_kernel(
        const float* __restrict__ fc1w, const float* __restrict__ fc1b,
        const float* __restrict__ fc2w, const float* __restrict__ fc2b,
        const float* __restrict__ fg, const float* __restrict__ fb,
        float* __restrict__ out) {
    float* w1 = dsm;                     // [64][257]  fc1^T padded
    float* w2 = dsm + 64*257;            // [256][65]  fc2^T padded
    float* x4 = w2 + 256*65;             // [4][64]
    float* h1 = x4 + 256;                // [4][256]
    __shared__ float ws[8], wq[8];
    int t = threadIdx.x;
    for (int i = t; i < MLPd*C1d; i += 256) {
        int j = i / C1d, k = i % C1d;
        w1[k*257 + j] = fc1w[i];
    }
    for (int i = t; i < C1d*MLPd; i += 256) {
        int c = i / MLPd, k = i % MLPd;
        w2[k*65 + c] = fc2w[i];
    }
    __syncthreads();
    int rblk = blockIdx.x;
    int r4 = t >> 6, ch = t & 63;
    int w = t >> 5, lane = t & 31;
    float gch = fg[ch], bch = fb[ch], b2c = fc2b[ch];
    float b1t = fc1b[t];
    for (int g = 0; g < 16; g++) {
        int row = rblk*64 + g*4 + r4;
        float cxv = g_cx[(size_t)row*C1d + ch];
        float s = cxv, q = cxv*cxv;
        #pragma unroll
        for (int o = 16; o > 0; o >>= 1) {
            s += __shfl_down_sync(0xffffffffu, s, o);
            q += __shfl_down_sync(0xffffffffu, q, o);
        }
        if (lane == 0) { ws[w] = s; wq[w] = q; }
        __syncthreads();
        float m  = (ws[2*r4] + ws[2*r4+1]) * (1.f/64);
        float vv = (wq[2*r4] + wq[2*r4+1]) * (1.f/64) - m*m;
        float rr = rsqrtf(vv + 1e-6f);
        x4[r4*64 + ch] = (cxv - m) * rr * gch + bch;
        __syncthreads();
        // fc1 + gelu: thread t = MLP column, all 4 rows
        float a0 = 0.f, a1 = 0.f, a2 = 0.f, a3 = 0.f;
        #pragma unroll 8
        for (int k = 0; k < 64; k++) {
            float wv = w1[k*257 + t];
            a0 += wv * x4[0*64 + k];
            a1 += wv * x4[1*64 + k];
            a2 += wv * x4[2*64 + k];
            a3 += wv * x4[3*64 + k];
        }
        h1[0*256 + t] = gelu_exact(a0 + b1t);
        h1[1*256 + t] = gelu_exact(a1 + b1t);
        h1[2*256 + t] = gelu_exact(a2 + b1t);
        h1[3*256 + t] = gelu_exact(a3 + b1t);
        __syncthreads();
        // fc2 + bias + residual
        float acc = 0.f;
        #pragma unroll 8
        for (int k = 0; k < 256; k++) acc += h1[r4*256 + k] * w2[k*65 + ch];
        out[(size_t)row*C1d + ch] = acc + b2c + cxv;
        __syncthreads();
    }
}

// ---------------- launch ----------------
extern "C" void kernel_launch(void* const* d_in, const int* in_sizes, int n_in,
                              void* d_out, int out_size) {
    const float* emb1   = (const float*)d_in[0];
    const float* emb2   = (const float*)d_in[1];
    const float* Wq     = (const float*)d_in[2];
    const float* Wk     = (const float*)d_in[3];
    const float* Wv     = (const float*)d_in[4];
    const float* Wout   = (const float*)d_in[5];
    const float* ln1_g  = (const float*)d_in[6];
    const float* ln1_b  = (const float*)d_in[7];
    const float* lnA_g  = (const float*)d_in[8];
    const float* lnA_b  = (const float*)d_in[9];
    const float* ffn_g  = (const float*)d_in[10];
    const float* ffn_b  = (const float*)d_in[11];
    const float* fc1_w  = (const float*)d_in[12];
    const float* fc1_b  = (const float*)d_in[13];
    const float* fc2_w  = (const float*)d_in[14];
    const float* fc2_b  = (const float*)d_in[15];
    float* out = (float*)d_out;

    const int smem_gmat = (64*64 + 64*192) * 4;          // 65536
    const int smem_tmat = (64*192 + 64*64) * 4;          // 65536
    const int smem_smat = (64*200 + 48*201) * 4;         // 89792
    const int smem_pmat = (64*200 + 192*48) * 4;         // 88064
    const int smem_mmat = (64*200 + 64*64) * 4;          // 67584
    const int smem_octx = (64*200 + 192*65) * 4;         // 101120
    const int smem_ffn  = (64*257 + 256*65 + 256 + 1024) * 4;  // 137472

    cudaFuncSetAttribute(gmat_kernel, cudaFuncAttributeMaxDynamicSharedMemorySize, smem_gmat);
    cudaFuncSetAttribute(tmat_kernel, cudaFuncAttributeMaxDynamicSharedMemorySize, smem_tmat);
    cudaFuncSetAttribute(smat_kernel, cudaFuncAttributeMaxDynamicSharedMemorySize, smem_smat);
    cudaFuncSetAttribute(pmat_kernel, cudaFuncAttributeMaxDynamicSharedMemorySize, smem_pmat);
    cudaFuncSetAttribute(mmat_kernel, cudaFuncAttributeMaxDynamicSharedMemorySize, smem_mmat);
    cudaFuncSetAttribute(octx_kernel, cudaFuncAttributeMaxDynamicSharedMemorySize, smem_octx);
    cudaFuncSetAttribute(ffn_kernel,  cudaFuncAttributeMaxDynamicSharedMemorySize, smem_ffn);

    dim3 t2(16, 16);

    ln_kernel<<<NROW, 192>>>(emb1, emb2, ln1_g, ln1_b, lnA_g, lnA_b);
    gmat_kernel<<<dim3(NCH, Bq), t2, smem_gmat>>>();
    gred_kernel<<<(Bq*GSZ)/256, 256>>>();
    tmat_kernel<<<Bq*Hh, t2, smem_tmat>>>(Wq);
    smat_kernel<<<dim3(Bq*Hh, 4), t2, smem_smat>>>(Wk);
    insoft_kernel<<<Bq*Hh, 256>>>();
    pmat_kernel<<<dim3(Bq*Hh, 4), t2, smem_pmat>>>(Wv);
    mmat_kernel<<<Bq, t2, smem_mmat>>>(Wout);
    octx_kernel<<<dim3(NCH, Bq), t2, smem_octx>>>(emb1);
    ffn_kernel<<<NROW/64, 256, smem_ffn>>>(fc1_w, fc1_b, fc2_w, fc2_b, ffn_g, ffn_b, out);
}

// round 2
// speedup vs baseline: 1.3654x; 1.3654x over previous
#include <cuda_runtime.h>
#include <math.h>

#define Bq   8
#define Nn   3136
#define C1d  64
#define C2d  128
#define KVd  192
#define Hh   4
#define MLPd 256
#define NROW (Bq*Nn)     /* 25088 */
#define NCH  49          /* 3136 / 64 */
#define GSZ  (C1d*KVd)   /* 12288 */

// ---------------- scratch (device globals; no allocation) ----------------
__device__ float g_ea[NROW*KVd];          // 19.3 MB  LN(concat) rows
__device__ float g_Gpart[Bq*NCH*GSZ];     // 19.3 MB  per-chunk partials of G
__device__ float g_G[Bq*GSZ];             //  G[b] = cx1^T @ ea
__device__ float g_T[Bq*Hh*GSZ];          //  T = Wq @ G
__device__ float g_S[Bq*Hh*GSZ];          //  scores -> probs (in place)
__device__ float g_Pp[Bq*Hh*GSZ];         //  probs @ Wv (per head)
__device__ float g_M[Bq*GSZ];             //  M[b] = Wout @ Pbar
__device__ float g_cx[NROW*C1d];          //  cx = emb1 + o

extern __shared__ float dsm[];

// ============ 1) fused dual-LayerNorm + G partial (cx1^T @ ea per 64 rows) ====
// grid (49, 8), 256 threads. cx1 never leaves smem.
__global__ __launch_bounds__(256,1) void gmatln_kernel(
        const float* __restrict__ emb1, const float* __restrict__ emb2,
        const float* __restrict__ g1, const float* __restrict__ b1,
        const float* __restrict__ gA, const float* __restrict__ bA) {
    float* sE = dsm;                 // [64][193] raw -> normalized ea
    float* sC = dsm + 64*193;        // [64][65]  cx1
    __shared__ float m1s[64], r1s[64], mAs[64], rAs[64];
    int ch = blockIdx.x, b = blockIdx.y;
    int base = b*Nn + ch*64;
    int tid = threadIdx.x;
    // stage raw concat rows
    for (int i = tid; i < 64*KVd; i += 256) {
        int r = i / KVd, c = i % KVd;
        float v = (c < C1d) ? emb1[(size_t)(base+r)*C1d + c]
                            : emb2[(size_t)(base+r)*C2d + (c - C1d)];
        sE[r*193 + c] = v;
    }
    __syncthreads();
    // per-row stats (64 threads, one row each)
    if (tid < 64) {
        float s1 = 0.f, q1 = 0.f, s2 = 0.f, q2 = 0.f;
        const float* row = sE + tid*193;
        #pragma unroll 8
        for (int c = 0; c < C1d; c++)  { float v = row[c]; s1 += v; q1 += v*v; }
        #pragma unroll 8
        for (int c = C1d; c < KVd; c++){ float v = row[c]; s2 += v; q2 += v*v; }
        float m1 = s1 * (1.f/C1d);
        float v1 = q1 * (1.f/C1d) - m1*m1;
        m1s[tid] = m1; r1s[tid] = rsqrtf(v1 + 1e-6f);
        float mA = (s1+s2) * (1.f/KVd);
        float vA = (q1+q2) * (1.f/KVd) - mA*mA;
        mAs[tid] = mA; rAs[tid] = rsqrtf(vA + 1e-6f);
    }
    __syncthreads();
    // normalize: ea (in smem + gmem), cx1 (smem only)
    for (int i = tid; i < 64*KVd; i += 256) {
        int r = i / KVd, c = i % KVd;
        float v = sE[r*193 + c];
        float ea = (v - mAs[r]) * rAs[r] * __ldg(gA + c) + __ldg(bA + c);
        sE[r*193 + c] = ea;
        g_ea[(size_t)(base+r)*KVd + c] = ea;
        if (c < C1d)
            sC[r*65 + c] = (v - m1s[r]) * r1s[r] * __ldg(g1 + c) + __ldg(b1 + c);
    }
    __syncthreads();
    // outer product partial: Gpart = sum_r cx1[r]^T ea[r]   (64x192)
    int x = tid & 15, y = tid >> 4;
    int cs = y*4, ks = x*12;
    float acc[4][12];
    #pragma unroll
    for (int j = 0; j < 4; j++)
        #pragma unroll
        for (int l = 0; l < 12; l++) acc[j][l] = 0.f;
    for (int r = 0; r < 64; r++) {
        float af[4], bf[12];
        #pragma unroll
        for (int j = 0; j < 4; j++) af[j] = sC[r*65 + cs + j];
        #pragma unroll
        for (int l = 0; l < 12; l++) bf[l] = sE[r*193 + ks + l];
        #pragma unroll
        for (int j = 0; j < 4; j++)
            #pragma unroll
            for (int l = 0; l < 12; l++) acc[j][l] += af[j]*bf[l];
    }
    float* out = g_Gpart + (size_t)(b*NCH + ch)*GSZ;
    #pragma unroll
    for (int j = 0; j < 4; j++)
        #pragma unroll
        for (int l = 0; l < 12; l++) out[(cs+j)*KVd + ks + l] = acc[j][l];
}

// ============ 2) reduce chunk partials ============
__global__ void gred_kernel() {
    int idx = blockIdx.x*256 + threadIdx.x;   // < 8*12288
    int b = idx / GSZ, e = idx % GSZ;
    const float* p = g_Gpart + (size_t)b*NCH*GSZ + e;
    float s = 0.f;
    #pragma unroll 7
    for (int ch = 0; ch < NCH; ch++) s += p[ch*GSZ];
    g_G[idx] = s;
}

// ============ 3) T = Wq[h] @ G[b]  (grid 32 x 4 col-tiles of 48) ============
__global__ __launch_bounds__(256,1) void tmat_kernel(const float* __restrict__ Wq) {
    float* sWT = dsm;                // [64][65]  Wq^T (c-major)
    float* sG  = dsm + 64*65;        // [64][52]  G col tile
    int bh = blockIdx.x, tile = blockIdx.y;
    int b = bh >> 2, h = bh & 3;
    int tid = threadIdx.x;
    for (int i = tid; i < C1d*C1d; i += 256) {
        int d = i / C1d, c = i % C1d;
        sWT[c*65 + d] = Wq[(size_t)h*C1d*C1d + i];
    }
    for (int i = tid; i < 64*48; i += 256) {
        int c = i / 48, k = i % 48;
        sG[c*52 + k] = g_G[(size_t)b*GSZ + c*KVd + tile*48 + k];
    }
    __syncthreads();
    int x = tid & 15, y = tid >> 4;
    int ds = y*4, kl = x*3;
    float acc[4][3];
    #pragma unroll
    for (int j = 0; j < 4; j++)
        #pragma unroll
        for (int l = 0; l < 3; l++) acc[j][l] = 0.f;
    for (int c = 0; c < C1d; c++) {
        float wf[4], gf[3];
        #pragma unroll
        for (int j = 0; j < 4; j++) wf[j] = sWT[c*65 + ds + j];
        #pragma unroll
        for (int l = 0; l < 3; l++) gf[l] = sG[c*52 + kl + l];
        #pragma unroll
        for (int j = 0; j < 4; j++)
            #pragma unroll
            for (int l = 0; l < 3; l++) acc[j][l] += wf[j]*gf[l];
    }
    float* out = g_T + (size_t)bh*GSZ;
    #pragma unroll
    for (int j = 0; j < 4; j++)
        #pragma unroll
        for (int l = 0; l < 3; l++)
            out[(ds+j)*KVd + tile*48 + kl + l] = acc[j][l];
}

// ============ 4) S = T @ Wk^T / sqrt(KV) ============
__global__ __launch_bounds__(256,1) void smat_kernel(const float* __restrict__ Wk) {
    float* sT  = dsm;                // [64][200]
    float* sWk = dsm + 64*200;       // [48][201]
    int bh = blockIdx.x, h = bh & 3;
    int tile = blockIdx.y;
    int tid = threadIdx.x;
    for (int i = tid; i < GSZ; i += 256) {
        int c = i / KVd, k = i % KVd;
        sT[c*200 + k] = g_T[(size_t)bh*GSZ + i];
    }
    for (int i = tid; i < 48*KVd; i += 256) {
        int r = i / KVd, k = i % KVd;
        sWk[r*201 + k] = Wk[(size_t)h*KVd*KVd + (tile*48 + r)*KVd + k];
    }
    __syncthreads();
    int x = tid & 15, y = tid >> 4;
    int cs = y*4, kl = x*3;
    float acc[4][3];
    #pragma unroll
    for (int j = 0; j < 4; j++)
        #pragma unroll
        for (int l = 0; l < 3; l++) acc[j][l] = 0.f;
    for (int kp = 0; kp < KVd; kp++) {
        float tf[4], wf[3];
        #pragma unroll
        for (int j = 0; j < 4; j++) tf[j] = sT[(cs+j)*200 + kp];
        #pragma unroll
        for (int l = 0; l < 3; l++) wf[l] = sWk[(kl+l)*201 + kp];
        #pragma unroll
        for (int j = 0; j < 4; j++)
            #pragma unroll
            for (int l = 0; l < 3; l++) acc[j][l] += tf[j]*wf[l];
    }
    const float scale = 0.0721687836487f;   // 1/sqrt(192)
    float* out = g_S + (size_t)bh*GSZ;
    #pragma unroll
    for (int j = 0; j < 4; j++)
        #pragma unroll
        for (int l = 0; l < 3; l++)
            out[(cs+j)*KVd + tile*48 + kl + l] = acc[j][l]*scale;
}

// ============ 5) InstanceNorm + softmax (in place) ============
__global__ void insoft_kernel() {
    int bh = blockIdx.x, t = threadIdx.x;
    float* S = g_S + (size_t)bh*GSZ;
    __shared__ float red[8];
    __shared__ float s_m, s_rs;
    int w = t >> 5, lane = t & 31;
    float s = 0.f;
    for (int i = t; i < GSZ; i += 256) s += S[i];
    #pragma unroll
    for (int o = 16; o > 0; o >>= 1) s += __shfl_down_sync(0xffffffffu, s, o);
    if (lane == 0) red[w] = s;
    __syncthreads();
    if (t == 0) {
        float tot = 0.f;
        for (int i = 0; i < 8; i++) tot += red[i];
        s_m = tot * (1.f/GSZ);
    }
    __syncthreads();
    float mean = s_m;
    float q = 0.f;
    for (int i = t; i < GSZ; i += 256) { float d = S[i] - mean; q += d*d; }
    #pragma unroll
    for (int o = 16; o > 0; o >>= 1) q += __shfl_down_sync(0xffffffffu, q, o);
    if (lane == 0) red[w] = q;
    __syncthreads();
    if (t == 0) {
        float tot = 0.f;
        for (int i = 0; i < 8; i++) tot += red[i];
        s_rs = rsqrtf(tot * (1.f/GSZ) + 1e-5f);
    }
    __syncthreads();
    float rs = s_rs;
    for (int r = w; r < C1d; r += 8) {
        float vals[6];
        float mx = -1e30f;
        #pragma unroll
        for (int mm = 0; mm < 6; mm++) {
            int k = lane + 32*mm;
            vals[mm] = (S[r*KVd + k] - mean) * rs;
            mx = fmaxf(mx, vals[mm]);
        }
        #pragma unroll
        for (int o = 16; o > 0; o >>= 1) mx = fmaxf(mx, __shfl_xor_sync(0xffffffffu, mx, o));
        float es = 0.f;
        #pragma unroll
        for (int mm = 0; mm < 6; mm++) { vals[mm] = expf(vals[mm] - mx); es += vals[mm]; }
        #pragma unroll
        for (int o = 16; o > 0; o >>= 1) es += __shfl_xor_sync(0xffffffffu, es, o);
        float inv = 1.f / es;
        #pragma unroll
        for (int mm = 0; mm < 6; mm++) S[r*KVd + lane + 32*mm] = vals[mm] * inv;
    }
}

// ============ 6) Pp[b,h] = probs @ Wv[h] ============
__global__ __launch_bounds__(256,1) void pmat_kernel(const float* __restrict__ Wv) {
    float* sP = dsm;                 // [64][200]
    float* sV = dsm + 64*200;        // [192][48]
    int bh = blockIdx.x, h = bh & 3, tile = blockIdx.y;
    int tid = threadIdx.x;
    for (int i = tid; i < GSZ; i += 256) {
        int c = i / KVd, k = i % KVd;
        sP[c*200 + k] = g_S[(size_t)bh*GSZ + i];
    }
    for (int i = tid; i < KVd*48; i += 256) {
        int k2 = i / 48, col = i % 48;
        sV[k2*48 + col] = Wv[(size_t)h*KVd*KVd + k2*KVd + tile*48 + col];
    }
    __syncthreads();
    int x = tid & 15, y = tid >> 4;
    int cs = y*4, kl = x*3;
    float acc[4][3];
    #pragma unroll
    for (int j = 0; j < 4; j++)
        #pragma unroll
        for (int l = 0; l < 3; l++) acc[j][l] = 0.f;
    for (int k2 = 0; k2 < KVd; k2++) {
        float pf[4], vf[3];
        #pragma unroll
        for (int j = 0; j < 4; j++) pf[j] = sP[(cs+j)*200 + k2];
        #pragma unroll
        for (int l = 0; l < 3; l++) vf[l] = sV[k2*48 + kl + l];
        #pragma unroll
        for (int j = 0; j < 4; j++)
            #pragma unroll
            for (int l = 0; l < 3; l++) acc[j][l] += pf[j]*vf[l];
    }
    float* out = g_Pp + (size_t)bh*GSZ;
    #pragma unroll
    for (int j = 0; j < 4; j++)
        #pragma unroll
        for (int l = 0; l < 3; l++)
            out[(cs+j)*KVd + tile*48 + kl + l] = acc[j][l];
}

// ============ 7) M[b] = Wout @ mean_h(Pp) ============
__global__ __launch_bounds__(256,1) void mmat_kernel(const float* __restrict__ Wout) {
    float* sP = dsm;                 // [64][200]
    float* sW = dsm + 64*200;        // [64][64]
    int b = blockIdx.x;
    int tid = threadIdx.x;
    for (int i = tid; i < GSZ; i += 256) {
        int c = i / KVd, k = i % KVd;
        float sum = g_Pp[(size_t)(b*Hh+0)*GSZ + i] + g_Pp[(size_t)(b*Hh+1)*GSZ + i]
                  + g_Pp[(size_t)(b*Hh+2)*GSZ + i] + g_Pp[(size_t)(b*Hh+3)*GSZ + i];
        sP[c*200 + k] = sum * 0.25f;
    }
    for (int i = tid; i < C1d*C1d; i += 256) sW[i] = Wout[i];
    __syncthreads();
    int x = tid & 15, y = tid >> 4;
    int ds = y*4, ks = x*12;
    float acc[4][12];
    #pragma unroll
    for (int j = 0; j < 4; j++)
        #pragma unroll
        for (int l = 0; l < 12; l++) acc[j][l] = 0.f;
    for (int c = 0; c < 64; c++) {
        float wf[4], pf[12];
        #pragma unroll
        for (int j = 0; j < 4; j++) wf[j] = sW[(ds+j)*C1d + c];
        #pragma unroll
        for (int l = 0; l < 12; l++) pf[l] = sP[c*200 + ks + l];
        #pragma unroll
        for (int j = 0; j < 4; j++)
            #pragma unroll
            for (int l = 0; l < 12; l++) acc[j][l] += wf[j]*pf[l];
    }
    float* out = g_M + (size_t)b*GSZ;
    #pragma unroll
    for (int j = 0; j < 4; j++)
        #pragma unroll
        for (int l = 0; l < 12; l++) out[(ds+j)*KVd + ks + l] = acc[j][l];
}

// ============ 8) cx = emb1 + ea @ M^T  (392 blocks, 64 rows, 4x4) ============
__global__ __launch_bounds__(256,1) void octx_kernel(const float* __restrict__ emb1) {
    float* sE  = dsm;                // [64][193]
    float* sMt = dsm + 64*193;       // [192][65]  (M transposed)
    int ch = blockIdx.x, b = blockIdx.y;
    int base = b*Nn + ch*64;
    int tid = threadIdx.x;
    for (int i = tid; i < 64*KVd; i += 256) {
        int r = i / KVd, k = i % KVd;
        sE[r*193 + k] = g_ea[(size_t)base*KVd + i];
    }
    for (int i = tid; i < GSZ; i += 256) {
        int c = i / KVd, k = i % KVd;
        sMt[k*65 + c] = g_M[(size_t)b*GSZ + i];
    }
    __syncthreads();
    int x = tid & 15, y = tid >> 4;
    int rs = y*4, cs = x*4;
    float acc[4][4];
    #pragma unroll
    for (int i = 0; i < 4; i++)
        #pragma unroll
        for (int j = 0; j < 4; j++) acc[i][j] = 0.f;
    for (int k = 0; k < KVd; k++) {
        float ef[4], mf[4];
        #pragma unroll
        for (int i = 0; i < 4; i++) ef[i] = sE[(rs+i)*193 + k];
        #pragma unroll
        for (int j = 0; j < 4; j++) mf[j] = sMt[k*65 + cs + j];
        #pragma unroll
        for (int i = 0; i < 4; i++)
            #pragma unroll
            for (int j = 0; j < 4; j++) acc[i][j] += ef[i]*mf[j];
    }
    #pragma unroll
    for (int i = 0; i < 4; i++) {
        int row = base + rs + i;
        #pragma unroll
        for (int j = 0; j < 4; j++)
            g_cx[(size_t)row*C1d + cs + j] = emb1[(size_t)row*C1d + cs + j] + acc[i][j];
    }
}

// ============ 9) fused FFN (64 rows/block, register-tiled) ============
__device__ __forceinline__ float gelu_exact(float x) {
    return 0.5f * x * (1.f + erff(x * 0.70710678118654752f));
}

__global__ __launch_bounds__(256,1) void ffn_kernel(
        const float* __restrict__ fc1w, const float* __restrict__ fc1b,
        const float* __restrict__ fc2w, const float* __restrict__ fc2b,
        const float* __restrict__ fg, const float* __restrict__ fb,
        float* __restrict__ out) {
    float* Xn  = dsm;                    // [64][65]  cx raw -> LN output
    float* Hs  = Xn + 64*65;             // [64][260] gelu(fc1) output
    float* W1s = Hs + 64*260;            // [64][258] fc1^T (k-major)
    float* W2s = W1s + 64*258;           // [256][65] fc2^T (k-major)
    __shared__ float ms[64], rss[64];
    int tid = threadIdx.x;
    int base = blockIdx.x*64;
    // weights
    for (int i = tid; i < MLPd*C1d; i += 256) {
        int j = i / C1d, k = i % C1d;
        W1s[k*258 + j] = fc1w[i];
    }
    for (int i = tid; i < C1d*MLPd; i += 256) {
        int c = i / MLPd, k = i % MLPd;
        W2s[k*65 + c] = fc2w[i];
    }
    // cx rows
    for (int i = tid; i < 64*C1d; i += 256) {
        int r = i >> 6, c = i & 63;
        Xn[r*65 + c] = g_cx[(size_t)(base+r)*C1d + c];
    }
    __syncthreads();
    // per-row LN stats
    if (tid < 64) {
        float s = 0.f, q = 0.f;
        const float* row = Xn + tid*65;
        #pragma unroll 8
        for (int c = 0; c < C1d; c++) { float v = row[c]; s += v; q += v*v; }
        float m = s * (1.f/C1d);
        float v = q * (1.f/C1d) - m*m;
        ms[tid] = m; rss[tid] = rsqrtf(v + 1e-6f);
    }
    __syncthreads();
    // normalize in place
    for (int i = tid; i < 64*C1d; i += 256) {
        int r = i >> 6, c = i & 63;
        Xn[r*65 + c] = (Xn[r*65 + c] - ms[r]) * rss[r] * __ldg(fg + c) + __ldg(fb + c);
    }
    __syncthreads();
    int x = tid & 15, y = tid >> 4;
    // fc1 + gelu: out tile 4 rows x 16 strided cols per thread
    {
        int rs = y*4;
        float acc[4][16];
        #pragma unroll
        for (int i = 0; i < 4; i++)
            #pragma unroll
            for (int j = 0; j < 16; j++) acc[i][j] = 0.f;
        for (int k = 0; k < C1d; k++) {
            float xr[4], wv[16];
            #pragma unroll
            for (int i = 0; i < 4; i++) xr[i] = Xn[(rs+i)*65 + k];
            #pragma unroll
            for (int j = 0; j < 16; j++) wv[j] = W1s[k*258 + x + 16*j];
            #pragma unroll
            for (int i = 0; i < 4; i++)
                #pragma unroll
                for (int j = 0; j < 16; j++) acc[i][j] += xr[i]*wv[j];
        }
        #pragma unroll
        for (int j = 0; j < 16; j++) {
            int col = x + 16*j;
            float bj = __ldg(fc1b + col);
            #pragma unroll
            for (int i = 0; i < 4; i++)
                Hs[(rs+i)*260 + col] = gelu_exact(acc[i][j] + bj);
        }
    }
    __syncthreads();
    // fc2 + bias + residual: out tile 4x4
    {
        int rs = y*4, cs = x*4;
        float acc[4][4];
        #pragma unroll
        for (int i = 0; i < 4; i++)
            #pragma unroll
            for (int j = 0; j < 4; j++) acc[i][j] = 0.f;
        for (int k = 0; k < MLPd; k++) {
            float hf[4], wf[4];
            #pragma unroll
            for (int i = 0; i < 4; i++) hf[i] = Hs[(rs+i)*260 + k];
            #pragma unroll
            for (int j = 0; j < 4; j++) wf[j] = W2s[k*65 + cs + j];
            #pragma unroll
            for (int i = 0; i < 4; i++)
                #pragma unroll
                for (int j = 0; j < 4; j++) acc[i][j] += hf[i]*wf[j];
        }
        #pragma unroll
        for (int i = 0; i < 4; i++) {
            int row = base + rs + i;
            #pragma unroll
            for (int j = 0; j < 4; j++) {
                int col = cs + j;
                out[(size_t)row*C1d + col] = acc[i][j] + __ldg(fc2b + col)
                                           + g_cx[(size_t)row*C1d + col];
            }
        }
    }
}

// ---------------- launch ----------------
extern "C" void kernel_launch(void* const* d_in, const int* in_sizes, int n_in,
                              void* d_out, int out_size) {
    const float* emb1   = (const float*)d_in[0];
    const float* emb2   = (const float*)d_in[1];
    const float* Wq     = (const float*)d_in[2];
    const float* Wk     = (const float*)d_in[3];
    const float* Wv     = (const float*)d_in[4];
    const float* Wout   = (const float*)d_in[5];
    const float* ln1_g  = (const float*)d_in[6];
    const float* ln1_b  = (const float*)d_in[7];
    const float* lnA_g  = (const float*)d_in[8];
    const float* lnA_b  = (const float*)d_in[9];
    const float* ffn_g  = (const float*)d_in[10];
    const float* ffn_b  = (const float*)d_in[11];
    const float* fc1_w  = (const float*)d_in[12];
    const float* fc1_b  = (const float*)d_in[13];
    const float* fc2_w  = (const float*)d_in[14];
    const float* fc2_b  = (const float*)d_in[15];
    float* out = (float*)d_out;

    const int smem_gmatln = (64*193 + 64*65) * 4;                   // 66048
    const int smem_tmat   = (64*65 + 64*52) * 4;                    // 29952
    const int smem_smat   = (64*200 + 48*201) * 4;                  // 89792
    const int smem_pmat   = (64*200 + 192*48) * 4;                  // 88064
    const int smem_mmat   = (64*200 + 64*64) * 4;                   // 67584
    const int smem_octx   = (64*193 + 192*65) * 4;                  // 99328
    const int smem_ffn    = (64*65 + 64*260 + 64*258 + 256*65) * 4; // 215808

    cudaFuncSetAttribute(gmatln_kernel, cudaFuncAttributeMaxDynamicSharedMemorySize, smem_gmatln);
    cudaFuncSetAttribute(smat_kernel,   cudaFuncAttributeMaxDynamicSharedMemorySize, smem_smat);
    cudaFuncSetAttribute(pmat_kernel,   cudaFuncAttributeMaxDynamicSharedMemorySize, smem_pmat);
    cudaFuncSetAttribute(mmat_kernel,   cudaFuncAttributeMaxDynamicSharedMemorySize, smem_mmat);
    cudaFuncSetAttribute(octx_kernel,   cudaFuncAttributeMaxDynamicSharedMemorySize, smem_octx);
    cudaFuncSetAttribute(ffn_kernel,    cudaFuncAttributeMaxDynamicSharedMemorySize, smem_ffn);

    gmatln_kernel<<<dim3(NCH, Bq), 256, smem_gmatln>>>(emb1, emb2, ln1_g, ln1_b, lnA_g, lnA_b);
    gred_kernel<<<(Bq*GSZ)/256, 256>>>();
    tmat_kernel<<<dim3(Bq*Hh, 4), 256, smem_tmat>>>(Wq);
    smat_kernel<<<dim3(Bq*Hh, 4), 256, smem_smat>>>(Wk);
    insoft_kernel<<<Bq*Hh, 256>>>();
    pmat_kernel<<<dim3(Bq*Hh, 4), 256, smem_pmat>>>(Wv);
    mmat_kernel<<<Bq, 256, smem_mmat>>>(Wout);
    octx_kernel<<<dim3(NCH, Bq), 256, smem_octx>>>(emb1);
    ffn_kernel<<<NROW/64, 256, smem_ffn>>>(fc1_w, fc1_b, fc2_w, fc2_b, ffn_g, ffn_b, out);
}

// round 3
// speedup vs baseline: 1.5084x; 1.1048x over previous
#include <cuda_runtime.h>
#include <math.h>

#define Bq   8
#define Nn   3136
#define C1d  64
#define C2d  128
#define KVd  192
#define Hh   4
#define MLPd 256
#define NROW (Bq*Nn)     /* 25088 */
#define NCH  49          /* 3136 / 64 */
#define GSZ  (C1d*KVd)   /* 12288 */

// ---------------- scratch (device globals; no allocation) ----------------
__device__ float g_ea[NROW*KVd];          // 19.3 MB  LN(concat) rows
__device__ float g_Gpart[Bq*NCH*GSZ];     // 19.3 MB  per-chunk partials of G
__device__ float g_G[Bq*GSZ];             //  G[b] = cx1^T @ ea
__device__ float g_S[Bq*Hh*GSZ];          //  scores (scaled, pre-IN)
__device__ float2 g_pstats[Bq*Hh*4];      //  per-tile (sum, sumsq) of scores
__device__ float g_Pp[Bq*Hh*GSZ];         //  probs @ Wv (per head)
__device__ float g_M[Bq*GSZ];             //  M[b] = Wout @ Pbar

extern __shared__ float dsm[];

// ============ 1) fused dual-LayerNorm + G partial (cx1^T @ ea per 64 rows) ====
__global__ __launch_bounds__(256,1) void gmatln_kernel(
        const float* __restrict__ emb1, const float* __restrict__ emb2,
        const float* __restrict__ g1, const float* __restrict__ b1,
        const float* __restrict__ gA, const float* __restrict__ bA) {
    float* sE = dsm;                 // [64][193] raw -> normalized ea
    float* sC = dsm + 64*193;        // [64][65]  cx1
    __shared__ float m1s[64], r1s[64], mAs[64], rAs[64];
    int ch = blockIdx.x, b = blockIdx.y;
    int base = b*Nn + ch*64;
    int tid = threadIdx.x;
    for (int i = tid; i < 64*KVd; i += 256) {
        int r = i / KVd, c = i % KVd;
        float v = (c < C1d) ? emb1[(size_t)(base+r)*C1d + c]
                            : emb2[(size_t)(base+r)*C2d + (c - C1d)];
        sE[r*193 + c] = v;
    }
    __syncthreads();
    if (tid < 64) {
        float s1 = 0.f, q1 = 0.f, s2 = 0.f, q2 = 0.f;
        const float* row = sE + tid*193;
        #pragma unroll 8
        for (int c = 0; c < C1d; c++)  { float v = row[c]; s1 += v; q1 += v*v; }
        #pragma unroll 8
        for (int c = C1d; c < KVd; c++){ float v = row[c]; s2 += v; q2 += v*v; }
        float m1 = s1 * (1.f/C1d);
        float v1 = q1 * (1.f/C1d) - m1*m1;
        m1s[tid] = m1; r1s[tid] = rsqrtf(v1 + 1e-6f);
        float mA = (s1+s2) * (1.f/KVd);
        float vA = (q1+q2) * (1.f/KVd) - mA*mA;
        mAs[tid] = mA; rAs[tid] = rsqrtf(vA + 1e-6f);
    }
    __syncthreads();
    for (int i = tid; i < 64*KVd; i += 256) {
        int r = i / KVd, c = i % KVd;
        float v = sE[r*193 + c];
        float ea = (v - mAs[r]) * rAs[r] * __ldg(gA + c) + __ldg(bA + c);
        sE[r*193 + c] = ea;
        g_ea[(size_t)(base+r)*KVd + c] = ea;
        if (c < C1d)
            sC[r*65 + c] = (v - m1s[r]) * r1s[r] * __ldg(g1 + c) + __ldg(b1 + c);
    }
    __syncthreads();
    int x = tid & 15, y = tid >> 4;
    int cs = y*4, ks = x*12;
    float acc[4][12];
    #pragma unroll
    for (int j = 0; j < 4; j++)
        #pragma unroll
        for (int l = 0; l < 12; l++) acc[j][l] = 0.f;
    for (int r = 0; r < 64; r++) {
        float af[4], bf[12];
        #pragma unroll
        for (int j = 0; j < 4; j++) af[j] = sC[r*65 + cs + j];
        #pragma unroll
        for (int l = 0; l < 12; l++) bf[l] = sE[r*193 + ks + l];
        #pragma unroll
        for (int j = 0; j < 4; j++)
            #pragma unroll
            for (int l = 0; l < 12; l++) acc[j][l] += af[j]*bf[l];
    }
    float* out = g_Gpart + (size_t)(b*NCH + ch)*GSZ;
    #pragma unroll
    for (int j = 0; j < 4; j++)
        #pragma unroll
        for (int l = 0; l < 12; l++) out[(cs+j)*KVd + ks + l] = acc[j][l];
}

// ============ 2) reduce chunk partials ============
__global__ void gred_kernel() {
    int idx = blockIdx.x*256 + threadIdx.x;
    int b = idx / GSZ, e = idx % GSZ;
    const float* p = g_Gpart + (size_t)b*NCH*GSZ + e;
    float s = 0.f;
    #pragma unroll 7
    for (int ch = 0; ch < NCH; ch++) s += p[ch*GSZ];
    g_G[idx] = s;
}

// ============ 3) fused T=Wq@G, S-tile = T@Wk^T/sqrt(KV) + partial stats =====
// grid (32, 4 tiles of 48 k2-cols), 256 threads
__global__ __launch_bounds__(256,1) void smatT_kernel(
        const float* __restrict__ Wq, const float* __restrict__ Wk) {
    float* sG  = dsm;                  // [64][196]
    float* sT  = dsm + 64*196;         // [64][196]
    float* sWq = sT + 64*196;          // [64][68]  Wq^T (c-major)
    float* sWk = sWq + 64*68;          // [48][197]
    __shared__ float redS[8], redQ[8];
    int bh = blockIdx.x, tile = blockIdx.y;
    int b = bh >> 2, h = bh & 3;
    int tid = threadIdx.x;
    for (int i = tid; i < GSZ; i += 256) {
        int c = i / KVd, k = i % KVd;
        sG[c*196 + k] = g_G[(size_t)b*GSZ + i];
    }
    for (int i = tid; i < C1d*C1d; i += 256) {
        int d = i >> 6, c = i & 63;
        sWq[c*68 + d] = Wq[(size_t)h*C1d*C1d + i];
    }
    for (int i = tid; i < 48*KVd; i += 256) {
        int r = i / KVd, k = i % KVd;
        sWk[r*197 + k] = Wk[(size_t)h*KVd*KVd + (tile*48 + r)*KVd + k];
    }
    __syncthreads();
    int x = tid & 15, y = tid >> 4;
    // Phase 1: T = Wq @ G, thread tile 4d x 12k
    {
        int ds = y*4, ks = x*12;
        float acc[4][12];
        #pragma unroll
        for (int j = 0; j < 4; j++)
            #pragma unroll
            for (int l = 0; l < 12; l++) acc[j][l] = 0.f;
        for (int c = 0; c < C1d; c++) {
            float wf[4];
            #pragma unroll
            for (int j = 0; j < 4; j++) wf[j] = sWq[c*68 + ds + j];
            const float4* gp = (const float4*)(sG + c*196 + ks);
            float4 g0 = gp[0], g1 = gp[1], g2 = gp[2];
            float gf[12] = {g0.x,g0.y,g0.z,g0.w, g1.x,g1.y,g1.z,g1.w, g2.x,g2.y,g2.z,g2.w};
            #pragma unroll
            for (int j = 0; j < 4; j++)
                #pragma unroll
                for (int l = 0; l < 12; l++) acc[j][l] += wf[j]*gf[l];
        }
        #pragma unroll
        for (int j = 0; j < 4; j++)
            #pragma unroll
            for (int l = 0; l < 12; l++) sT[(ds+j)*196 + ks + l] = acc[j][l];
    }
    __syncthreads();
    // Phase 2: S tile = T @ Wk^T * scale, thread tile 4c x 3k2
    const float scale = 0.0721687836487f;   // 1/sqrt(192)
    int cs = y*4, kl = x*3;
    float acc2[4][3];
    #pragma unroll
    for (int j = 0; j < 4; j++)
        #pragma unroll
        for (int l = 0; l < 3; l++) acc2[j][l] = 0.f;
    for (int kp = 0; kp < KVd; kp++) {
        float tf[4], wf[3];
        #pragma unroll
        for (int j = 0; j < 4; j++) tf[j] = sT[(cs+j)*196 + kp];
        #pragma unroll
        for (int l = 0; l < 3; l++) wf[l] = sWk[(kl+l)*197 + kp];
        #pragma unroll
        for (int j = 0; j < 4; j++)
            #pragma unroll
            for (int l = 0; l < 3; l++) acc2[j][l] += tf[j]*wf[l];
    }
    float lsum = 0.f, lsq = 0.f;
    float* out = g_S + (size_t)bh*GSZ;
    #pragma unroll
    for (int j = 0; j < 4; j++)
        #pragma unroll
        for (int l = 0; l < 3; l++) {
            float v = acc2[j][l]*scale;
            out[(cs+j)*KVd + tile*48 + kl + l] = v;
            lsum += v; lsq += v*v;
        }
    // block-reduce partial stats
    int w = tid >> 5, lane = tid & 31;
    #pragma unroll
    for (int o = 16; o > 0; o >>= 1) {
        lsum += __shfl_down_sync(0xffffffffu, lsum, o);
        lsq  += __shfl_down_sync(0xffffffffu, lsq, o);
    }
    if (lane == 0) { redS[w] = lsum; redQ[w] = lsq; }
    __syncthreads();
    if (tid == 0) {
        float s = 0.f, q = 0.f;
        #pragma unroll
        for (int i = 0; i < 8; i++) { s += redS[i]; q += redQ[i]; }
        g_pstats[bh*4 + tile] = make_float2(s, q);
    }
}

// ============ 4) fused InstanceNorm + softmax + Pp-tile = probs @ Wv ========
// grid (32, 4), 256 threads
__global__ __launch_bounds__(256,1) void pmat_kernel(const float* __restrict__ Wv) {
    float* sS = dsm;                   // [64][196] scores -> probs
    float* sV = dsm + 64*196;          // [192][52]
    __shared__ float s_m, s_rs;
    int bh = blockIdx.x, h = bh & 3, tile = blockIdx.y;
    int tid = threadIdx.x;
    for (int i = tid; i < GSZ; i += 256) {
        int c = i / KVd, k = i % KVd;
        sS[c*196 + k] = g_S[(size_t)bh*GSZ + i];
    }
    for (int i = tid; i < KVd*48; i += 256) {
        int k = i / 48, col = i % 48;
        sV[k*52 + col] = Wv[(size_t)h*KVd*KVd + k*KVd + tile*48 + col];
    }
    if (tid == 0) {
        float s = 0.f, q = 0.f;
        #pragma unroll
        for (int t = 0; t < 4; t++) {
            float2 p = g_pstats[bh*4 + t];
            s += p.x; q += p.y;
        }
        float m = s * (1.f/GSZ);
        float v = q * (1.f/GSZ) - m*m;
        s_m = m; s_rs = rsqrtf(v + 1e-5f);
    }
    __syncthreads();
    float mean = s_m, rs = s_rs;
    // IN + softmax per row, in smem
    int w = tid >> 5, lane = tid & 31;
    for (int r = w; r < C1d; r += 8) {
        float vals[6];
        float mx = -1e30f;
        #pragma unroll
        for (int mm = 0; mm < 6; mm++) {
            vals[mm] = (sS[r*196 + lane + 32*mm] - mean) * rs;
            mx = fmaxf(mx, vals[mm]);
        }
        #pragma unroll
        for (int o = 16; o > 0; o >>= 1) mx = fmaxf(mx, __shfl_xor_sync(0xffffffffu, mx, o));
        float es = 0.f;
        #pragma unroll
        for (int mm = 0; mm < 6; mm++) { vals[mm] = __expf(vals[mm] - mx); es += vals[mm]; }
        #pragma unroll
        for (int o = 16; o > 0; o >>= 1) es += __shfl_xor_sync(0xffffffffu, es, o);
        float inv = 1.f / es;
        #pragma unroll
        for (int mm = 0; mm < 6; mm++) sS[r*196 + lane + 32*mm] = vals[mm] * inv;
    }
    __syncthreads();
    // Pp tile = probs @ Wv, thread tile 4c x 3k2
    int x = tid & 15, y = tid >> 4;
    int cs = y*4, kl = x*3;
    float acc[4][3];
    #pragma unroll
    for (int j = 0; j < 4; j++)
        #pragma unroll
        for (int l = 0; l < 3; l++) acc[j][l] = 0.f;
    for (int kp = 0; kp < KVd; kp++) {
        float pf[4], vf[3];
        #pragma unroll
        for (int j = 0; j < 4; j++) pf[j] = sS[(cs+j)*196 + kp];
        #pragma unroll
        for (int l = 0; l < 3; l++) vf[l] = sV[kp*52 + kl + l];
        #pragma unroll
        for (int j = 0; j < 4; j++)
            #pragma unroll
            for (int l = 0; l < 3; l++) acc[j][l] += pf[j]*vf[l];
    }
    float* out = g_Pp + (size_t)bh*GSZ;
    #pragma unroll
    for (int j = 0; j < 4; j++)
        #pragma unroll
        for (int l = 0; l < 3; l++)
            out[(cs+j)*KVd + tile*48 + kl + l] = acc[j][l];
}

// ============ 5) M[b] = Wout @ mean_h(Pp) ============
__global__ __launch_bounds__(256,1) void mmat_kernel(const float* __restrict__ Wout) {
    float* sP = dsm;                 // [64][200]
    float* sW = dsm + 64*200;        // [64][64]
    int b = blockIdx.x;
    int tid = threadIdx.x;
    for (int i = tid; i < GSZ; i += 256) {
        int c = i / KVd, k = i % KVd;
        float sum = g_Pp[(size_t)(b*Hh+0)*GSZ + i] + g_Pp[(size_t)(b*Hh+1)*GSZ + i]
                  + g_Pp[(size_t)(b*Hh+2)*GSZ + i] + g_Pp[(size_t)(b*Hh+3)*GSZ + i];
        sP[c*200 + k] = sum * 0.25f;
    }
    for (int i = tid; i < C1d*C1d; i += 256) sW[i] = Wout[i];
    __syncthreads();
    int x = tid & 15, y = tid >> 4;
    int ds = y*4, ks = x*12;
    float acc[4][12];
    #pragma unroll
    for (int j = 0; j < 4; j++)
        #pragma unroll
        for (int l = 0; l < 12; l++) acc[j][l] = 0.f;
    for (int c = 0; c < 64; c++) {
        float wf[4], pf[12];
        #pragma unroll
        for (int j = 0; j < 4; j++) wf[j] = sW[(ds+j)*C1d + c];
        #pragma unroll
        for (int l = 0; l < 12; l++) pf[l] = sP[c*200 + ks + l];
        #pragma unroll
        for (int j = 0; j < 4; j++)
            #pragma unroll
            for (int l = 0; l < 12; l++) acc[j][l] += wf[j]*pf[l];
    }
    float* out = g_M + (size_t)b*GSZ;
    #pragma unroll
    for (int j = 0; j < 4; j++)
        #pragma unroll
        for (int l = 0; l < 12; l++) out[(ds+j)*KVd + ks + l] = acc[j][l];
}

// ============ 6) fused tail: cx = emb1 + ea@M^T ; out = FFN(cx) + cx ========
__device__ __forceinline__ float gelu_exact(float x) {
    return 0.5f * x * (1.f + erff(x * 0.70710678118654752f));
}

// smem float offsets
#define T_HS   0                      /* Hs [64][260] = 16640 ; alias sEA [64][196]=12544 */
#define T_W1   16640                  /* W1 [64][258] = 16512 ; alias sMt [192][68]=13056 */
#define T_W2   33152                  /* W2 [256][68] = 17408 */
#define T_XN   50560                  /* Xn [64][65]  = 4160  */
#define T_TOT  54720                  /* *4 = 218880 B */

__global__ __launch_bounds__(256,1) void tail_kernel(
        const float* __restrict__ emb1,
        const float* __restrict__ fc1w, const float* __restrict__ fc1b,
        const float* __restrict__ fc2w, const float* __restrict__ fc2b,
        const float* __restrict__ fg, const float* __restrict__ fb,
        float* __restrict__ out) {
    float* sEA = dsm + T_HS;           // [64][196]
    float* sMt = dsm + T_W1;           // [192][68]  M^T
    float* W2s = dsm + T_W2;           // [256][68]  fc2^T (k-major rows)
    float* W1s = dsm + T_W1;           // [64][258]  (after octx)
    float* Hs  = dsm + T_HS;           // [64][260]  (after octx)
    float* Xn  = dsm + T_XN;           // [64][65]
    __shared__ float ms[64], rss[64];
    int ch = blockIdx.x, b = blockIdx.y;
    int base = b*Nn + ch*64;
    int tid = threadIdx.x;
    int x = tid & 15, y = tid >> 4;
    // load ea tile, M^T, and preload W2 (region free during octx)
    for (int i = tid; i < 64*KVd; i += 256) {
        int r = i / KVd, k = i % KVd;
        sEA[r*196 + k] = g_ea[(size_t)base*KVd + i];
    }
    for (int i = tid; i < GSZ; i += 256) {
        int c = i / KVd, k = i % KVd;
        sMt[k*68 + c] = g_M[(size_t)b*GSZ + i];
    }
    for (int i = tid; i < C1d*MLPd; i += 256) {
        int c = i >> 8, k = i & 255;
        W2s[k*68 + c] = fc2w[i];
    }
    __syncthreads();
    // octx: cx tile (4x4) in registers
    float cx[4][4];
    {
        int rs = y*4, cs = x*4;
        float acc[4][4];
        #pragma unroll
        for (int i = 0; i < 4; i++)
            #pragma unroll
            for (int j = 0; j < 4; j++) acc[i][j] = 0.f;
        for (int k = 0; k < KVd; k++) {
            float ef[4];
            #pragma unroll
            for (int i = 0; i < 4; i++) ef[i] = sEA[(rs+i)*196 + k];
            float4 mf = *(const float4*)(sMt + k*68 + cs);
            #pragma unroll
            for (int i = 0; i < 4; i++) {
                acc[i][0] += ef[i]*mf.x;
                acc[i][1] += ef[i]*mf.y;
                acc[i][2] += ef[i]*mf.z;
                acc[i][3] += ef[i]*mf.w;
            }
        }
        #pragma unroll
        for (int i = 0; i < 4; i++) {
            float4 e = *(const float4*)(emb1 + (size_t)(base+rs+i)*C1d + cs);
            cx[i][0] = e.x + acc[i][0];
            cx[i][1] = e.y + acc[i][1];
            cx[i][2] = e.z + acc[i][2];
            cx[i][3] = e.w + acc[i][3];
            #pragma unroll
            for (int j = 0; j < 4; j++) Xn[(rs+i)*65 + cs + j] = cx[i][j];
        }
    }
    __syncthreads();
    // load W1 (overwrites sMt region); LN stats
    for (int i = tid; i < MLPd*C1d; i += 256) {
        int d = i >> 6, k = i & 63;
        W1s[k*258 + d] = fc1w[i];
    }
    if (tid < 64) {
        float s = 0.f, q = 0.f;
        const float* row = Xn + tid*65;
        #pragma unroll 8
        for (int c = 0; c < C1d; c++) { float v = row[c]; s += v; q += v*v; }
        float m = s * (1.f/C1d);
        float v = q * (1.f/C1d) - m*m;
        ms[tid] = m; rss[tid] = rsqrtf(v + 1e-6f);
    }
    __syncthreads();
    for (int i = tid; i < 64*C1d; i += 256) {
        int r = i >> 6, c = i & 63;
        Xn[r*65 + c] = (Xn[r*65 + c] - ms[r]) * rss[r] * __ldg(fg + c) + __ldg(fb + c);
    }
    __syncthreads();
    // fc1 + gelu (4 rows x 16 strided cols); Hs overwrites sEA region
    {
        int rs = y*4;
        float acc[4][16];
        #pragma unroll
        for (int i = 0; i < 4; i++)
            #pragma unroll
            for (int j = 0; j < 16; j++) acc[i][j] = 0.f;
        for (int k = 0; k < C1d; k++) {
            float xr[4], wv[16];
            #pragma unroll
            for (int i = 0; i < 4; i++) xr[i] = Xn[(rs+i)*65 + k];
            #pragma unroll
            for (int j = 0; j < 16; j++) wv[j] = W1s[k*258 + x + 16*j];
            #pragma unroll
            for (int i = 0; i < 4; i++)
                #pragma unroll
                for (int j = 0; j < 16; j++) acc[i][j] += xr[i]*wv[j];
        }
        #pragma unroll
        for (int j = 0; j < 16; j++) {
            int col = x + 16*j;
            float bj = __ldg(fc1b + col);
            #pragma unroll
            for (int i = 0; i < 4; i++)
                Hs[(rs+i)*260 + col] = gelu_exact(acc[i][j] + bj);
        }
    }
    __syncthreads();
    // fc2 + bias + residual (registers)
    {
        int rs = y*4, cs = x*4;
        float acc[4][4];
        #pragma unroll
        for (int i = 0; i < 4; i++)
            #pragma unroll
            for (int j = 0; j < 4; j++) acc[i][j] = 0.f;
        for (int k = 0; k < MLPd; k++) {
            float hf[4];
            #pragma unroll
            for (int i = 0; i < 4; i++) hf[i] = Hs[(rs+i)*260 + k];
            float4 wf = *(const float4*)(W2s + k*68 + cs);
            #pragma unroll
            for (int i = 0; i < 4; i++) {
                acc[i][0] += hf[i]*wf.x;
                acc[i][1] += hf[i]*wf.y;
                acc[i][2] += hf[i]*wf.z;
                acc[i][3] += hf[i]*wf.w;
            }
        }
        float4 b2 = *(const float4*)(fc2b + cs);
        #pragma unroll
        for (int i = 0; i < 4; i++) {
            float4 o;
            o.x = acc[i][0] + b2.x + cx[i][0];
            o.y = acc[i][1] + b2.y + cx[i][1];
            o.z = acc[i][2] + b2.z + cx[i][2];
            o.w = acc[i][3] + b2.w + cx[i][3];
            *(float4*)(out + (size_t)(base+rs+i)*C1d + cs) = o;
        }
    }
}

// ---------------- launch ----------------
extern "C" void kernel_launch(void* const* d_in, const int* in_sizes, int n_in,
                              void* d_out, int out_size) {
    const float* emb1   = (const float*)d_in[0];
    const float* emb2   = (const float*)d_in[1];
    const float* Wq     = (const float*)d_in[2];
    const float* Wk     = (const float*)d_in[3];
    const float* Wv     = (const float*)d_in[4];
    const float* Wout   = (const float*)d_in[5];
    const float* ln1_g  = (const float*)d_in[6];
    const float* ln1_b  = (const float*)d_in[7];
    const float* lnA_g  = (const float*)d_in[8];
    const float* lnA_b  = (const float*)d_in[9];
    const float* ffn_g  = (const float*)d_in[10];
    const float* ffn_b  = (const float*)d_in[11];
    const float* fc1_w  = (const float*)d_in[12];
    const float* fc1_b  = (const float*)d_in[13];
    const float* fc2_w  = (const float*)d_in[14];
    const float* fc2_b  = (const float*)d_in[15];
    float* out = (float*)d_out;

    const int smem_gmatln = (64*193 + 64*65) * 4;                    // 66048
    const int smem_smatT  = (64*196 + 64*196 + 64*68 + 48*197) * 4;  // 155584
    const int smem_pmat   = (64*196 + 192*52) * 4;                   // 90112
    const int smem_mmat   = (64*200 + 64*64) * 4;                    // 67584
    const int smem_tail   = T_TOT * 4;                               // 218880

    cudaFuncSetAttribute(gmatln_kernel, cudaFuncAttributeMaxDynamicSharedMemorySize, smem_gmatln);
    cudaFuncSetAttribute(smatT_kernel,  cudaFuncAttributeMaxDynamicSharedMemorySize, smem_smatT);
    cudaFuncSetAttribute(pmat_kernel,   cudaFuncAttributeMaxDynamicSharedMemorySize, smem_pmat);
    cudaFuncSetAttribute(mmat_kernel,   cudaFuncAttributeMaxDynamicSharedMemorySize, smem_mmat);
    cudaFuncSetAttribute(tail_kernel,   cudaFuncAttributeMaxDynamicSharedMemorySize, smem_tail);

    gmatln_kernel<<<dim3(NCH, Bq), 256, smem_gmatln>>>(emb1, emb2, ln1_g, ln1_b, lnA_g, lnA_b);
    gred_kernel<<<(Bq*GSZ)/256, 256>>>();
    smatT_kernel<<<dim3(Bq*Hh, 4), 256, smem_smatT>>>(Wq, Wk);
    pmat_kernel<<<dim3(Bq*Hh, 4), 256, smem_pmat>>>(Wv);
    mmat_kernel<<<Bq, 256, smem_mmat>>>(Wout);
    tail_kernel<<<dim3(NCH, Bq), 256, smem_tail>>>(emb1, fc1_w, fc1_b, fc2_w, fc2_b, ffn_g, ffn_b, out);
}